// round 14
// baseline (speedup 1.0000x reference)
#include <cuda_runtime.h>
#include <cuda_fp16.h>
#include <cstdint>

// DenseMRConv: out = x @ (Wt - Wb) + (max_k x_j) @ Wb + b
// k1: x -> fp16 shadow. k2: warp-cooperative wide gather (LDG.128 = 4 rows)
// + packed f32x2 GEMM epilogue. MB=12 nodes/warp as 6 pairs, 4 blocks/SM.

#define WPB 8
#define THREADS (WPB * 32)
#define D 64
#define KNBR 32
#define NP 6            // node pairs per warp
#define MB (2 * NP)
#define MAXN 100000

__device__ __half2 g_xh[MAXN * (D / 2)];   // 12.8 MB fp16 shadow of x

#define WP_F4 2048
#define HP_BYTES (NP * 64 * 8)             // 3 KB per warp
#define SMEM_BYTES (WP_F4 * 16 + WPB * HP_BYTES)

__global__ void __launch_bounds__(256) convert_kernel(const float2* __restrict__ x2, int n2) {
    const int e = blockIdx.x * 256 + threadIdx.x;
    if (e < n2) {
        const float2 v = x2[e];
        g_xh[e] = __floats2half2_rn(v.x, v.y);
    }
}

__device__ __forceinline__ void fma2(unsigned long long& d,
                                     unsigned long long a, unsigned long long b) {
    asm("fma.rn.f32x2 %0, %1, %2, %0;" : "+l"(d) : "l"(a), "l"(b));
}
__device__ __forceinline__ unsigned long long pack2(float v) {
    unsigned long long r;
    asm("mov.b64 %0, {%1, %1};" : "=l"(r) : "f"(v));
    return r;
}
__device__ __forceinline__ float2 unpack2(unsigned long long v) {
    float2 r;
    asm("mov.b64 {%0, %1}, %2;" : "=f"(r.x), "=f"(r.y) : "l"(v));
    return r;
}
__device__ __forceinline__ __half2 hshflx(__half2 v, int m) {
    const unsigned u = __shfl_xor_sync(0xffffffffu, *(const unsigned*)&v, m);
    return *(const __half2*)&u;
}

// One epilogue pass over 64 dims. hp: pair-major u64{h[n0][d],h[n1][d]}.
__device__ __forceinline__ void epi_pass(const float4* __restrict__ Wp, int t0,
                                         const ulonglong2* __restrict__ hp, int lane,
                                         unsigned long long acc[NP][2]) {
    #pragma unroll 2
    for (int t = 0; t < 16; t++) {
        const float4 wA = Wp[(t0 + t) * 64 + lane];        // dims 4t,4t+1 cols 2l,2l+1
        const float4 wB = Wp[(t0 + t) * 64 + 32 + lane];   // dims 4t+2,4t+3
        const unsigned long long aAx = pack2(wA.x), aAy = pack2(wA.y);
        const unsigned long long aAz = pack2(wA.z), aAw = pack2(wA.w);
        const unsigned long long aBx = pack2(wB.x), aBy = pack2(wB.y);
        const unsigned long long aBz = pack2(wB.z), aBw = pack2(wB.w);
        #pragma unroll
        for (int p = 0; p < NP; p++) {
            const ulonglong2 U0 = hp[p * 32 + 2 * t];
            const ulonglong2 U1 = hp[p * 32 + 2 * t + 1];
            fma2(acc[p][0], U0.x, aAx); fma2(acc[p][1], U0.x, aAy);
            fma2(acc[p][0], U0.y, aAz); fma2(acc[p][1], U0.y, aAw);
            fma2(acc[p][0], U1.x, aBx); fma2(acc[p][1], U1.x, aBy);
            fma2(acc[p][0], U1.y, aBz); fma2(acc[p][1], U1.y, aBw);
        }
    }
}

__global__ void __launch_bounds__(THREADS, 4) mrconv_kernel(
    const float* __restrict__ x,
    const int* __restrict__ edge_index,
    const float* __restrict__ W,
    const float* __restrict__ b,
    float* __restrict__ out,
    int N)
{
    extern __shared__ float4 sm[];
    float4* __restrict__ Wp = sm;                       // W' permuted, 32 KB
    char* hpb = (char*)(sm + WP_F4);                    // 3 KB per warp

    const int tid  = threadIdx.x;
    const int warp = tid >> 5;
    const int lane = tid & 31;

    // Stage W': rows 0..63 = Wt - Wb, rows 64..127 = Wb.
    {
        const float2* W2 = (const float2*)W;
        for (int e = tid; e < WP_F4; e += THREADS) {
            const int l  = e & 31;
            const int h  = (e >> 5) & 1;
            const int t  = e >> 6;
            const int db = 4 * t + 2 * h;
            float2 a0 = W2[db * 32 + l];
            float2 a1 = W2[(db + 1) * 32 + l];
            if (db < 64) {
                const float2 s0 = W2[(db + 64) * 32 + l];
                const float2 s1 = W2[(db + 65) * 32 + l];
                a0.x -= s0.x; a0.y -= s0.y;
                a1.x -= s1.x; a1.y -= s1.y;
            }
            Wp[e] = make_float4(a0.x, a0.y, a1.x, a1.y);
        }
    }
    __syncthreads();

    const unsigned long long bb0 = pack2(b[2 * lane]);
    const unsigned long long bb1 = pack2(b[2 * lane + 1]);

    const float2* __restrict__ x2 = (const float2*)x;
    float2* __restrict__ out2     = (float2*)out;

    float4*           hp4 = (float4*)(hpb + warp * HP_BYTES);
    const ulonglong2* hpu = (const ulonglong2*)(hpb + warp * HP_BYTES);

    const int gwarp  = blockIdx.x * WPB + warp;
    const int nwarps = gridDim.x * WPB;

    const __half2 hneg = __floats2half2_rn(-INFINITY, -INFINITY);
    const int sub2 = (lane >> 3) & 1;        // neighbor-parity sub-group
    const int h16  = lane & 16;              // node half: 0 = node A, 16 = node B
    const int half = h16 >> 4;               // 0 / 1
    const int bl   = lane & 7;               // 16B slice within row (dims 8bl..8bl+7)

    for (int i0 = gwarp * MB; i0 < N; i0 += nwarps * MB) {
        // --- Phase 1: cooperative gather + stage mx pairs (pair-major u64) ---
        #pragma unroll
        for (int p = 0; p < NP; p++) {
            const int iA = min(i0 + 2 * p, N - 1);
            const int iB = min(i0 + 2 * p + 1, N - 1);
            const int rA = edge_index[iA * KNBR + lane];
            const int rB = edge_index[iB * KNBR + lane];
            // s0: lanes0-15 = A[0..15], lanes16-31 = B[0..15]
            // s1: lanes0-15 = A[16..31], lanes16-31 = B[16..31]
            const int blo = __shfl_sync(0xffffffffu, rB, lane & 15);
            const int ahi = __shfl_sync(0xffffffffu, rA, 16 | (lane & 15));
            const int s0 = (lane < 16) ? rA : blo;
            const int s1 = (lane < 16) ? ahi : rB;

            __half2 m0 = hneg, m1 = hneg, m2 = hneg, m3 = hneg;
            #pragma unroll
            for (int t = 0; t < 16; t++) {
                const int kk  = 2 * t + sub2;               // neighbor slot
                const int src = (kk & 15) | h16;
                const int j   = __shfl_sync(0xffffffffu, (t < 8) ? s0 : s1, src);
                const float4 v = __ldcg((const float4*)(g_xh + j * (D / 2)) + bl);
                const __half2* q = (const __half2*)&v;
                m0 = __hmax2(m0, q[0]); m1 = __hmax2(m1, q[1]);
                m2 = __hmax2(m2, q[2]); m3 = __hmax2(m3, q[3]);
            }
            // reduce across sub2 partner (lane ^ 8): full max over 32 neighbors
            m0 = __hmax2(m0, hshflx(m0, 8)); m1 = __hmax2(m1, hshflx(m1, 8));
            m2 = __hmax2(m2, hshflx(m2, 8)); m3 = __hmax2(m3, hshflx(m3, 8));

            // Exchange groups chosen by sub2 ONLY (bit4-invariant): xor-16
            // partner holds the SAME dim group for the other node.
            const __half2 ga = sub2 ? m2 : m0;   // group 2*sub2
            const __half2 gb = sub2 ? m3 : m1;   // group 2*sub2+1
            const __half2 ga_o = hshflx(ga, 16);
            const __half2 gb_o = hshflx(gb, 16);
            const __half2 vA = half ? gb_o : ga;
            const __half2 vB = half ? gb   : ga_o;
            const float2 fa = __half22float2(vA);
            const float2 fb = __half22float2(vB);
            hp4[p * 32 + 4 * bl + 2 * sub2 + half] = make_float4(fa.x, fb.x, fa.y, fb.y);
        }
        __syncwarp();

        unsigned long long acc[NP][2];
        #pragma unroll
        for (int p = 0; p < NP; p++) { acc[p][0] = bb0; acc[p][1] = bb1; }

        // --- Pass B: h = mx, W' rows 64..127 ---
        epi_pass(Wp, 16, hpu, lane, acc);
        __syncwarp();

        // --- Stage x pairs (lane owns dims 2l,2l+1) ---
        #pragma unroll
        for (int p = 0; p < NP; p++) {
            const int iA = min(i0 + 2 * p, N - 1);
            const int iB = min(i0 + 2 * p + 1, N - 1);
            const float2 xa = x2[iA * (D / 2) + lane];
            const float2 xb = x2[iB * (D / 2) + lane];
            hp4[p * 32 + lane] = make_float4(xa.x, xb.x, xa.y, xb.y);
        }
        __syncwarp();

        // --- Pass A: h = x, W' rows 0..63 ---
        epi_pass(Wp, 0, hpu, lane, acc);

        // --- Store ---
        #pragma unroll
        for (int p = 0; p < NP; p++) {
            const float2 c0 = unpack2(acc[p][0]);
            const float2 c1 = unpack2(acc[p][1]);
            const int iA = i0 + 2 * p, iB = iA + 1;
            if (iA < N) out2[iA * (D / 2) + lane] = make_float2(c0.x, c1.x);
            if (iB < N) out2[iB * (D / 2) + lane] = make_float2(c0.y, c1.y);
        }
        __syncwarp();
    }
}

extern "C" void kernel_launch(void* const* d_in, const int* in_sizes, int n_in,
                              void* d_out, int out_size) {
    const float* x  = (const float*)d_in[0];
    const int*   ei = (const int*)d_in[1];
    const float* W  = (const float*)d_in[2];
    const float* b  = (const float*)d_in[3];
    float* out = (float*)d_out;

    const int N = in_sizes[0] / D;
    const int n2 = N * (D / 2);

    static int smem_set = 0;
    if (!smem_set) {
        cudaFuncSetAttribute(mrconv_kernel,
                             cudaFuncAttributeMaxDynamicSharedMemorySize, SMEM_BYTES);
        smem_set = 1;
    }

    convert_kernel<<<(n2 + 255) / 256, 256>>>((const float2*)x, n2);

    // 56 KB smem, <=64 regs -> 4 blocks/SM, 152 SMs
    const int grid = 608;
    mrconv_kernel<<<grid, THREADS, SMEM_BYTES>>>(x, ei, W, b, out, N);
}

// round 15
// speedup vs baseline: 1.3795x; 1.3795x over previous
#include <cuda_runtime.h>
#include <cuda_fp16.h>
#include <cstdint>

// DenseMRConv: out = [x | max_k x_j] @ W' + b,  W' = [Wt-Wb ; Wb]
// k1: x -> fp16 shadow. k2: cooperative wide gather (R13) + mma.sync HMMA
// epilogue: per warp-batch of 16 nodes, A=[16x128] fp16 in smem, B=W' fp16
// in smem (ldmatrix), 8x8 mma.m16n8k16 into fp32 accs.

#define WPB 8
#define THREADS 256
#define D 64
#define KNBR 32
#define MB 16
#define NPAIR 8
#define MAXN 100000

__device__ __half2 g_xh[MAXN * 32];   // 12.8 MB fp16 shadow of x

#define BS_STRIDE 272                 // 128 half + 8 pad (bank-rotate)
#define BS_BYTES  (64 * BS_STRIDE)    // 17408
#define BIAS_OFF  BS_BYTES
#define HB_OFF    (BS_BYTES + 256)
#define HB_STRIDE 272
#define HB_WARP   (MB * HB_STRIDE)    // 4352
#define SMEM_BYTES (HB_OFF + WPB * HB_WARP)   // 52480

__global__ void __launch_bounds__(256) convert_kernel(const float2* __restrict__ x2, int n2) {
    const int e = blockIdx.x * 256 + threadIdx.x;
    if (e < n2) {
        const float2 v = x2[e];
        g_xh[e] = __floats2half2_rn(v.x, v.y);
    }
}

__device__ __forceinline__ uint32_t smem_u32(const void* p) {
    uint32_t a;
    asm("{ .reg .u64 t; cvta.to.shared.u64 t, %1; cvt.u32.u64 %0, t; }" : "=r"(a) : "l"(p));
    return a;
}
__device__ __forceinline__ __half2 hshflx(__half2 v, int m) {
    const unsigned u = __shfl_xor_sync(0xffffffffu, *(const unsigned*)&v, m);
    return *(const __half2*)&u;
}

__global__ void __launch_bounds__(THREADS, 4) mrconv_kernel(
    const float* __restrict__ x,
    const int* __restrict__ edge_index,
    const float* __restrict__ W,
    const float* __restrict__ b,
    float* __restrict__ out,
    int N)
{
    extern __shared__ char smem[];
    const uint32_t smb = smem_u32(smem);

    const int tid  = threadIdx.x;
    const int warp = tid >> 5;
    const int lane = tid & 31;

    // Stage B = W'^T fp16: Bs[c][d] = W'[d][c]; W'[0:64]=Wt-Wb, W'[64:128]=Wb
    for (int e = tid; e < 128 * 64; e += THREADS) {
        const int d = e >> 6, c = e & 63;
        float w = W[e];
        if (d < 64) w -= W[e + 64 * 64];
        *(__half*)(smem + c * BS_STRIDE + d * 2) = __float2half_rn(w);
    }
    if (tid < 64) ((float*)(smem + BIAS_OFF))[tid] = b[tid];
    __syncthreads();

    char* hb = smem + HB_OFF + warp * HB_WARP;
    const uint32_t hb_u = smb + HB_OFF + warp * HB_WARP;

    float2* __restrict__ out2 = (float2*)out;
    const float2* bias2 = (const float2*)(smem + BIAS_OFF);

    const int gwarp  = blockIdx.x * WPB + warp;
    const int nwarps = gridDim.x * WPB;
    const int nbt = (N + MB - 1) / MB;

    const __half2 hneg = __floats2half2_rn(-INFINITY, -INFINITY);
    const int sub2 = (lane >> 3) & 1;
    const int h16  = lane & 16;
    const int half = h16 >> 4;
    const int bl   = lane & 7;
    const int egrp = 4 * bl + 2 * sub2 + half;   // mx dim group: dims 2e,2e+1

    for (int bt = gwarp; bt < nbt; bt += nwarps) {
        const int i0 = bt * MB;

        // --- Stage x part of A: hb[n][0:64] fp16 straight from shadow ---
        #pragma unroll
        for (int n = 0; n < MB; n++) {
            const int i = min(i0 + n, N - 1);
            const uint32_t xv = *(const uint32_t*)&g_xh[i * 32 + lane];
            *(uint32_t*)(hb + n * HB_STRIDE + 4 * lane) = xv;
        }

        // --- Cooperative wide gather (R13-proven) + stage mx to hb[n][64:128] ---
        #pragma unroll
        for (int p = 0; p < NPAIR; p++) {
            const int iA = min(i0 + 2 * p, N - 1);
            const int iB = min(i0 + 2 * p + 1, N - 1);
            const int rA = edge_index[iA * KNBR + lane];
            const int rB = edge_index[iB * KNBR + lane];
            const int blo = __shfl_sync(0xffffffffu, rB, lane & 15);
            const int ahi = __shfl_sync(0xffffffffu, rA, 16 | (lane & 15));
            const int s0 = (lane < 16) ? rA : blo;
            const int s1 = (lane < 16) ? ahi : rB;

            __half2 m0 = hneg, m1 = hneg, m2 = hneg, m3 = hneg;
            #pragma unroll
            for (int t = 0; t < 16; t++) {
                const int kk  = 2 * t + sub2;
                const int src = (kk & 15) | h16;
                const int j   = __shfl_sync(0xffffffffu, (t < 8) ? s0 : s1, src);
                const float4 v = __ldcg((const float4*)(g_xh + j * 32) + bl);
                const __half2* q = (const __half2*)&v;
                m0 = __hmax2(m0, q[0]); m1 = __hmax2(m1, q[1]);
                m2 = __hmax2(m2, q[2]); m3 = __hmax2(m3, q[3]);
            }
            m0 = __hmax2(m0, hshflx(m0, 8)); m1 = __hmax2(m1, hshflx(m1, 8));
            m2 = __hmax2(m2, hshflx(m2, 8)); m3 = __hmax2(m3, hshflx(m3, 8));

            const __half2 ga = sub2 ? m2 : m0;
            const __half2 gb = sub2 ? m3 : m1;
            const __half2 ga_o = hshflx(ga, 16);
            const __half2 gb_o = hshflx(gb, 16);
            const __half2 vA = half ? gb_o : ga;
            const __half2 vB = half ? gb   : ga_o;
            *(uint32_t*)(hb + (2 * p)     * HB_STRIDE + 128 + 4 * egrp) = *(const uint32_t*)&vA;
            *(uint32_t*)(hb + (2 * p + 1) * HB_STRIDE + 128 + 4 * egrp) = *(const uint32_t*)&vB;
        }
        __syncwarp();

        // --- MMA: acc[nb] (16x8 f32) = A(16x128) @ B(128x64) ---
        float acc[8][4];
        #pragma unroll
        for (int nb = 0; nb < 8; nb++)
            acc[nb][0] = acc[nb][1] = acc[nb][2] = acc[nb][3] = 0.0f;

        #pragma unroll
        for (int kk = 0; kk < 8; kk++) {
            uint32_t a0, a1, a2, a3;
            const uint32_t aaddr = hb_u + (lane & 15) * HB_STRIDE + 32 * kk
                                 + ((lane >> 4) & 1) * 16;
            asm volatile("ldmatrix.sync.aligned.m8n8.x4.shared.b16 {%0,%1,%2,%3}, [%4];"
                         : "=r"(a0), "=r"(a1), "=r"(a2), "=r"(a3) : "r"(aaddr));
            #pragma unroll
            for (int nb = 0; nb < 8; nb++) {
                uint32_t b0, b1;
                const uint32_t baddr = smb + (8 * nb + (lane & 7)) * BS_STRIDE
                                     + 32 * kk + ((lane >> 3) & 1) * 16;
                asm volatile("ldmatrix.sync.aligned.m8n8.x2.shared.b16 {%0,%1}, [%2];"
                             : "=r"(b0), "=r"(b1) : "r"(baddr));
                asm volatile(
                    "mma.sync.aligned.m16n8k16.row.col.f32.f16.f16.f32 "
                    "{%0,%1,%2,%3}, {%4,%5,%6,%7}, {%8,%9}, {%0,%1,%2,%3};"
                    : "+f"(acc[nb][0]), "+f"(acc[nb][1]), "+f"(acc[nb][2]), "+f"(acc[nb][3])
                    : "r"(a0), "r"(a1), "r"(a2), "r"(a3), "r"(b0), "r"(b1));
            }
        }

        // --- Store: lane covers rows l/4, l/4+8; cols 8nb+2(l%4)+{0,1} ---
        const int r0 = lane >> 2;
        const int cq = lane & 3;
        #pragma unroll
        for (int nb = 0; nb < 8; nb++) {
            const float2 bv = bias2[4 * nb + cq];
            const int col2 = 4 * nb + cq;
            const int iA = i0 + r0, iB = i0 + r0 + 8;
            if (iA < N) out2[iA * 32 + col2] =
                make_float2(acc[nb][0] + bv.x, acc[nb][1] + bv.y);
            if (iB < N) out2[iB * 32 + col2] =
                make_float2(acc[nb][2] + bv.x, acc[nb][3] + bv.y);
        }
        __syncwarp();   // hb reused next batch
    }
}

extern "C" void kernel_launch(void* const* d_in, const int* in_sizes, int n_in,
                              void* d_out, int out_size) {
    const float* x  = (const float*)d_in[0];
    const int*   ei = (const int*)d_in[1];
    const float* W  = (const float*)d_in[2];
    const float* b  = (const float*)d_in[3];
    float* out = (float*)d_out;

    const int N = in_sizes[0] / D;
    const int n2 = N * 32;

    static int smem_set = 0;
    if (!smem_set) {
        cudaFuncSetAttribute(mrconv_kernel,
                             cudaFuncAttributeMaxDynamicSharedMemorySize, SMEM_BYTES);
        smem_set = 1;
    }

    convert_kernel<<<(n2 + 255) / 256, 256>>>((const float2*)x, n2);

    // 6250 batches of 16; 391 blocks * 8 warps = 3128 warps -> 2 batches each
    const int nbt = (N + MB - 1) / MB;
    int grid = (nbt + 2 * WPB - 1) / (2 * WPB);
    if (grid > 608) grid = 608;
    if (grid < 1) grid = 1;
    mrconv_kernel<<<grid, THREADS, SMEM_BYTES>>>(x, ei, W, b, out, N);
}